// round 7
// baseline (speedup 1.0000x reference)
#include <cuda_runtime.h>
#include <cuda_bf16.h>

#define B   32
#define U   32
#define TK  64
#define TDEC 64
#define D   512
#define V   50257

// ---------------- scratch ----------------
__device__ float g_local_dec[B*D];
__device__ float g_dec_ua[B*D];
__device__ float g_dec_ta[B*D];
__device__ float g_target_out[B*D];
__device__ int   g_sel[B];
__device__ float g_logits[(long)B*V];
__device__ float g_m[B];
__device__ float g_inv_s[B];
__device__ unsigned g_hhi[B*256];   // [b][kpair] bf16x2 of h_hi
__device__ unsigned g_hlo[B*256];   // [b][kpair] bf16x2 of h_lo

// ---------------- helpers ----------------
__device__ __forceinline__ float ftanh(float x){
    float y; asm("tanh.approx.f32 %0, %1;" : "=f"(y) : "f"(x)); return y;
}
__device__ __forceinline__ float wsum(float v){
    #pragma unroll
    for (int o=16;o;o>>=1) v += __shfl_xor_sync(0xffffffffu, v, o);
    return v;
}
__device__ __forceinline__ float wmax(float v){
    #pragma unroll
    for (int o=16;o;o>>=1) v = fmaxf(v, __shfl_xor_sync(0xffffffffu, v, o));
    return v;
}
__device__ __forceinline__ unsigned smem_u32(const void* p){
    unsigned a;
    asm("{ .reg .u64 t; cvta.to.shared.u64 t, %1; cvt.u32.u64 %0, t; }" : "=r"(a) : "l"(p));
    return a;
}

// cp.async
#define CPA(dst, src) asm volatile("cp.async.cg.shared.global [%0], [%1], 16;" :: "r"(dst), "l"(src) : "memory")
#define CPC()  asm volatile("cp.async.commit_group;" ::: "memory")
#define CPW2() asm volatile("cp.async.wait_group 2;" ::: "memory")

// bf16 mma m16n8k16
__device__ __forceinline__ void mma16816(float* d, unsigned a0, unsigned a1,
                                         unsigned a2, unsigned a3,
                                         unsigned b0, unsigned b1){
    asm volatile("mma.sync.aligned.m16n8k16.row.col.f32.bf16.bf16.f32 "
        "{%0,%1,%2,%3}, {%4,%5,%6,%7}, {%8,%9}, {%0,%1,%2,%3};"
        : "+f"(d[0]), "+f"(d[1]), "+f"(d[2]), "+f"(d[3])
        : "r"(a0), "r"(a1), "r"(a2), "r"(a3), "r"(b0), "r"(b1));
}
__device__ __forceinline__ void cvt_hilo(float2 f, unsigned &hi, unsigned &lo){
    __nv_bfloat162 h = __float22bfloat162_rn(f);
    float2 fh = __bfloat1622float2(h);
    __nv_bfloat162 l = __float22bfloat162_rn(make_float2(f.x - fh.x, f.y - fh.y));
    hi = *(unsigned*)&h; lo = *(unsigned*)&l;
}

// ---------------- K1: layernorm ----------------
__global__ void k_ln(const float* __restrict__ tf, const float* __restrict__ g,
                     const float* __restrict__ bb){
    int b = blockIdx.x, tid = threadIdx.x;
    const float* row = tf + (b*TDEC + (TDEC-1))*D;
    float x0 = row[tid], x1 = row[tid+256];
    __shared__ float s1[256], s2[256];
    s1[tid] = x0+x1; s2[tid] = x0*x0 + x1*x1;
    __syncthreads();
    for (int o=128;o;o>>=1){
        if (tid<o){ s1[tid]+=s1[tid+o]; s2[tid]+=s2[tid+o]; }
        __syncthreads();
    }
    float mu = s1[0]*(1.0f/D);
    float var = s2[0]*(1.0f/D) - mu*mu;
    float r = rsqrtf(var + 1e-5f);
    g_local_dec[b*D+tid]     = (x0-mu)*r*g[tid]     + bb[tid];
    g_local_dec[b*D+tid+256] = (x1-mu)*r*g[tid+256] + bb[tid+256];
}

// ---------------- K2: dec projections (W rows in regs, 8 batches/block) ------
__global__ void k_proj(const float* __restrict__ ua_Wp, const float* __restrict__ ua_bp,
                       const float* __restrict__ ta_Wp, const float* __restrict__ ta_bp){
    int which = blockIdx.z;
    const float* W    = which ? ta_Wp : ua_Wp;
    const float* bias = which ? ta_bp : ua_bp;
    float* outp       = which ? g_dec_ta : g_dec_ua;
    int warp = threadIdx.x >> 5, lane = threadIdx.x & 31;
    int d = blockIdx.x*8 + warp;
    const float4* wrow = (const float4*)(W + (long)d*D);
    float4 w4[4];
    #pragma unroll
    for (int i=0;i<4;i++) w4[i] = wrow[i*32 + lane];
    float bval = bias[d];
    #pragma unroll
    for (int bi=0; bi<8; bi++){
        int b = blockIdx.y*8 + bi;
        const float4* t = (const float4*)(g_local_dec + b*D);
        float acc = 0.f;
        #pragma unroll
        for (int i=0;i<4;i++){
            float4 t4 = t[i*32 + lane];
            acc += w4[i].x*t4.x + w4[i].y*t4.y + w4[i].z*t4.z + w4[i].w*t4.w;
        }
        acc = wsum(acc);
        if (!lane) outp[b*D + d] = acc + bval;
    }
}

// ---------------- K3: utterance attention + argmax + p_gen ----------------
__global__ void k_uatt(const float* __restrict__ enc, const float* __restrict__ umask,
                       const float* __restrict__ cov, const float* __restrict__ ua_wc,
                       const float* __restrict__ ua_v, const float* __restrict__ pgen_W,
                       const float* __restrict__ pgen_b,
                       float* __restrict__ o_ucov, float* __restrict__ o_pgen,
                       float* __restrict__ o_uidx){
    int b = blockIdx.x, tid = threadIdx.x;
    int warp = tid>>5, lane = tid&31;
    __shared__ float s_scores[U], s_attn[U], s_red[256];
    float4 dec4[4], wc4[4], v4[4];
    #pragma unroll
    for (int i=0;i<4;i++){
        int d = i*128 + lane*4;
        dec4[i] = *(const float4*)(g_dec_ua + b*D + d);
        wc4[i]  = *(const float4*)(ua_wc + d);
        v4[i]   = *(const float4*)(ua_v + d);
    }
    #pragma unroll
    for (int uu=0; uu<4; uu++){
        int u = warp + uu*8;
        float c = cov[b*U + u];
        const float4* e = (const float4*)(enc + (long)(b*U + u)*D);
        float acc = 0.f;
        #pragma unroll
        for (int i=0;i<4;i++){
            float4 x = e[i*32 + lane];
            acc += ftanh(x.x + dec4[i].x + c*wc4[i].x) * v4[i].x;
            acc += ftanh(x.y + dec4[i].y + c*wc4[i].y) * v4[i].y;
            acc += ftanh(x.z + dec4[i].z + c*wc4[i].z) * v4[i].z;
            acc += ftanh(x.w + dec4[i].w + c*wc4[i].w) * v4[i].w;
        }
        acc = wsum(acc);
        if (!lane) s_scores[u] = acc;
    }
    __syncthreads();
    if (warp == 0){
        int u = lane;
        float s = s_scores[u];
        float m = wmax(s);
        float e = expf(s - m);
        float den = wsum(e);
        float a_ = (e/den) * umask[b*U+u];
        float nf = wsum(a_);
        float attn = a_ / (nf == 0.f ? 1.f : nf);
        s_attn[u] = attn;
        o_ucov[b*U+u] = cov[b*U+u] + attn;
        float bv = attn; int bi = u;
        #pragma unroll
        for (int o=16;o;o>>=1){
            float ov = __shfl_xor_sync(0xffffffffu, bv, o);
            int   oi = __shfl_xor_sync(0xffffffffu, bi, o);
            if (ov > bv || (ov == bv && oi < bi)){ bv = ov; bi = oi; }
        }
        if (!lane){ g_sel[b] = bi; o_uidx[b] = (float)bi; }
    }
    __syncthreads();
    float part = 0.f;
    #pragma unroll
    for (int j=0;j<2;j++){
        int d = tid + j*256;
        float acc = 0.f;
        #pragma unroll 8
        for (int u=0;u<U;u++) acc += s_attn[u] * enc[(long)(b*U+u)*D + d];
        part += pgen_W[d]*acc + pgen_W[D + d]*g_local_dec[b*D + d];
    }
    s_red[tid] = part;
    __syncthreads();
    for (int o=128;o;o>>=1){ if (tid<o) s_red[tid]+=s_red[tid+o]; __syncthreads(); }
    if (!tid) o_pgen[b] = 1.f/(1.f + expf(-(s_red[0] + pgen_b[0])));
}

// ---------------- K4: token attention (3-stage ring, 4 blocks/SM) ------------
// CRITICAL: one commit group per iteration (unconditional CPC) so that
// wait_group 2 at iteration tt guarantees groups 0..tt complete -> row tt ready.
__global__ void __launch_bounds__(256,4)
k_tatt(const float* __restrict__ tok, const float* __restrict__ tmask,
       const float* __restrict__ tcov, const float* __restrict__ ta_wc,
       const float* __restrict__ ta_v,
       float* __restrict__ o_ntc, float* __restrict__ o_tattn){
    extern __shared__ float ring[];   // 8 warps * 3 stages * 512 floats = 48KB
    __shared__ float s_wc[D], s_v[D];
    __shared__ float s_scores[TK], s_attn[TK], s_cov[TK];
    int u = blockIdx.x, b = blockIdx.y;
    int tid = threadIdx.x, warp = tid>>5, lane = tid&31;
    int ub = u*B + b;
    float* wring = ring + warp*1536;
    unsigned rb = smem_u32(wring);
    const float* rowbase = tok + (long)ub*TK*D;

    // ring prologue: rows 0..2 per warp (3 commit groups)
    #pragma unroll
    for (int s=0;s<3;s++){
        const float* src = rowbase + (warp*8+s)*D;
        #pragma unroll
        for (int i=0;i<4;i++)
            CPA(rb + (unsigned)(s*512 + (i*32+lane)*4)*4u, src + (i*32+lane)*4);
        CPC();
    }
    // stage params
    for (int i=tid; i<D; i+=256){ s_wc[i] = ta_wc[i]; s_v[i] = ta_v[i]; }
    if (tid < TK) s_cov[tid] = tcov[ub*TK + tid];
    float4 dec4[4];
    #pragma unroll
    for (int i=0;i<4;i++)
        dec4[i] = *(const float4*)(g_dec_ta + b*D + i*128 + lane*4);
    __syncthreads();

    const float4* sw = (const float4*)s_wc;
    const float4* sv = (const float4*)s_v;
    #pragma unroll
    for (int tt=0; tt<8; tt++){
        CPW2();   // groups 0..tt complete -> row tt resident in stage tt%3
        float c = s_cov[warp*8+tt];
        const float4* xs = (const float4*)(wring + (tt%3)*512);
        float acc = 0.f;
        #pragma unroll
        for (int i=0;i<4;i++){
            float4 x = xs[i*32+lane];
            float4 wc = sw[i*32+lane], vv = sv[i*32+lane];
            acc += ftanh(x.x + dec4[i].x + c*wc.x)*vv.x;
            acc += ftanh(x.y + dec4[i].y + c*wc.y)*vv.y;
            acc += ftanh(x.z + dec4[i].z + c*wc.z)*vv.z;
            acc += ftanh(x.w + dec4[i].w + c*wc.w)*vv.w;
        }
        acc = wsum(acc);
        if (!lane) s_scores[warp*8+tt] = acc;
        if (tt < 5){   // refill freed stage with row tt+3
            const float* src = rowbase + (warp*8+tt+3)*D;
            unsigned st = (unsigned)(tt%3);
            #pragma unroll
            for (int i=0;i<4;i++)
                CPA(rb + (st*512 + (unsigned)(i*32+lane)*4)*4u, src + (i*32+lane)*4);
        }
        CPC();   // UNCONDITIONAL: exactly one group per iteration
    }
    __syncthreads();
    int sel = g_sel[b];
    if (warp == 0){
        float s0 = s_scores[lane], s1 = s_scores[lane+32];
        float m = wmax(fmaxf(s0,s1));
        float e0 = expf(s0-m), e1 = expf(s1-m);
        float den = wsum(e0+e1);
        float a0 = (e0/den)*tmask[ub*TK+lane];
        float a1 = (e1/den)*tmask[ub*TK+lane+32];
        float nf = wsum(a0+a1);
        float inv = 1.f/((nf==0.f)?1.f:nf);
        a0 *= inv; a1 *= inv;
        s_attn[lane] = a0; s_attn[lane+32] = a1;
        o_ntc[ub*TK+lane]    = s_cov[lane]    + a0;
        o_ntc[ub*TK+lane+32] = s_cov[lane+32] + a1;
        if (u == sel){ o_tattn[b*TK+lane] = a0; o_tattn[b*TK+lane+32] = a1; }
    }
    __syncthreads();
    if (u == sel){
        #pragma unroll
        for (int j=0;j<2;j++){
            int d = tid + j*256;
            float acc = 0.f;
            #pragma unroll 8
            for (int t=0;t<TK;t++) acc += s_attn[t]*tok[(long)ub*TK*D + t*D + d];
            g_target_out[b*D + d] = acc;
        }
    }
}

// ---------------- K5: h -> bf16 hi/lo (W1 rows in regs, 8 batches/block) -----
__global__ void k_h(const float* __restrict__ W1, const float* __restrict__ b1){
    int warp = threadIdx.x>>5, lane = threadIdx.x&31;
    int d = blockIdx.x*8 + warp;
    const float4* w = (const float4*)(W1 + (long)d*2*D);
    float4 w4[8];
    #pragma unroll
    for (int i=0;i<8;i++) w4[i] = w[i*32+lane];
    float bval = b1[d];
    #pragma unroll
    for (int bi=0; bi<8; bi++){
        int b = blockIdx.y*8 + bi;
        const float4* t0 = (const float4*)(g_target_out + b*D);
        const float4* t1 = (const float4*)(g_local_dec + b*D);
        float acc=0.f;
        #pragma unroll
        for (int i=0;i<4;i++){
            float4 x = t0[i*32+lane];
            acc += w4[i].x*x.x + w4[i].y*x.y + w4[i].z*x.z + w4[i].w*x.w;
        }
        #pragma unroll
        for (int i=0;i<4;i++){
            float4 x = t1[i*32+lane];
            acc += w4[i+4].x*x.x + w4[i+4].y*x.y + w4[i+4].z*x.z + w4[i+4].w*x.w;
        }
        acc = wsum(acc);
        if (!lane){
            float h = acc + bval;
            __nv_bfloat16 hi = __float2bfloat16(h);
            __nv_bfloat16 lo = __float2bfloat16(h - __bfloat162float(hi));
            ((__nv_bfloat16*)g_hhi)[b*512 + d] = hi;
            ((__nv_bfloat16*)g_hlo)[b*512 + d] = lo;
        }
    }
}

// ---------------- K6: vocab GEMM via mma.sync (depth-2 A prefetch) -----------
#define BSTRIDE 260
__global__ void __launch_bounds__(256)
k_vocab(const float* __restrict__ W2, const float* __restrict__ b2){
    extern __shared__ uint2 sB[];   // 32 * 260 * 8B = 66560 B
    int tid = threadIdx.x, wm = tid>>5, lane = tid&31;
    int g = lane>>2, tg = lane&3;
    int v0 = blockIdx.x * 128;

    for (int i = tid; i < 32*256; i += 256){
        int n = i >> 8, kp = i & 255;
        sB[n*BSTRIDE + kp] = make_uint2(g_hhi[i], g_hlo[i]);
    }
    __syncthreads();

    int r0 = v0 + wm*16 + g;
    int r1 = r0 + 8;
    const float* w0 = W2 + (long)(r0 < V ? r0 : V-1)*D;
    const float* w1 = W2 + (long)(r1 < V ? r1 : V-1)*D;

    float dd[4][4];
    #pragma unroll
    for (int nt=0;nt<4;nt++){ dd[nt][0]=dd[nt][1]=dd[nt][2]=dd[nt][3]=0.f; }

    int c0 = tg*2;
    float2 pa[2][4];
    #pragma unroll
    for (int s=0;s<2;s++){
        int kn = s*16 + c0;
        pa[s][0] = *(const float2*)(w0 + kn);
        pa[s][1] = *(const float2*)(w1 + kn);
        pa[s][2] = *(const float2*)(w0 + kn + 8);
        pa[s][3] = *(const float2*)(w1 + kn + 8);
    }

    #pragma unroll 4
    for (int ks=0; ks<32; ks++){
        int buf = ks & 1;
        float2 ca0=pa[buf][0], ca1=pa[buf][1], ca2=pa[buf][2], ca3=pa[buf][3];
        if (ks + 2 < 32){
            int kn = (ks+2)*16 + c0;
            pa[buf][0] = *(const float2*)(w0 + kn);
            pa[buf][1] = *(const float2*)(w1 + kn);
            pa[buf][2] = *(const float2*)(w0 + kn + 8);
            pa[buf][3] = *(const float2*)(w1 + kn + 8);
        }

        unsigned ah0,al0,ah1,al1,ah2,al2,ah3,al3;
        cvt_hilo(ca0, ah0, al0);
        cvt_hilo(ca1, ah1, al1);
        cvt_hilo(ca2, ah2, al2);
        cvt_hilo(ca3, ah3, al3);

        int kp = ks*8 + tg;
        #pragma unroll
        for (int nt=0; nt<4; nt++){
            int nrow = (nt*8 + g)*BSTRIDE;
            uint2 b0 = sB[nrow + kp];
            uint2 b1 = sB[nrow + kp + 4];
            mma16816(dd[nt], ah0, ah1, ah2, ah3, b0.x, b1.x);  // hi*hi
            mma16816(dd[nt], al0, al1, al2, al3, b0.x, b1.x);  // lo*hi
            mma16816(dd[nt], ah0, ah1, ah2, ah3, b0.y, b1.y);  // hi*lo
        }
    }

    float bias0 = (r0 < V) ? b2[r0] : 0.f;
    float bias1 = (r1 < V) ? b2[r1] : 0.f;
    #pragma unroll
    for (int nt=0; nt<4; nt++){
        int n = nt*8 + tg*2;
        if (r0 < V){
            g_logits[(long)n*V + r0]     = dd[nt][0] + bias0;
            g_logits[(long)(n+1)*V + r0] = dd[nt][1] + bias0;
        }
        if (r1 < V){
            g_logits[(long)n*V + r1]     = dd[nt][2] + bias1;
            g_logits[(long)(n+1)*V + r1] = dd[nt][3] + bias1;
        }
    }
}

// ---------------- K7: softmax stats ----------------
__global__ void k_red(){
    int b = blockIdx.x, tid = threadIdx.x;
    __shared__ float sm[256];
    const float* L = g_logits + (long)b*V;
    float m = -1e30f;
    for (int v=tid; v<V; v+=256) m = fmaxf(m, L[v]);
    sm[tid]=m; __syncthreads();
    for (int o=128;o;o>>=1){ if (tid<o) sm[tid]=fmaxf(sm[tid],sm[tid+o]); __syncthreads(); }
    m = sm[0]; __syncthreads();
    float s=0.f;
    for (int v=tid; v<V; v+=256) s += expf(L[v]-m);
    sm[tid]=s; __syncthreads();
    for (int o=128;o;o>>=1){ if (tid<o) sm[tid]+=sm[tid+o]; __syncthreads(); }
    if (!tid){ g_m[b]=m; g_inv_s[b] = 1.f/sm[0]; }
}

// ---------------- K8: vocab_dist ----------------
__global__ void k_soft(float* __restrict__ o_vocab){
    long i = (long)blockIdx.x*256 + threadIdx.x;
    if (i >= (long)B*V) return;
    int b = (int)(i / V);
    o_vocab[i] = expf(g_logits[i] - g_m[b]) * g_inv_s[b];
}

// ---------------- launch ----------------
extern "C" void kernel_launch(void* const* d_in, const int* in_sizes, int n_in,
                              void* d_out, int out_size){
    const float* tf    = (const float*)d_in[0];
    const float* enc   = (const float*)d_in[2];
    const float* umask = (const float*)d_in[3];
    const float* tok   = (const float*)d_in[4];
    const float* tmask = (const float*)d_in[5];
    const float* cov   = (const float*)d_in[6];
    const float* tcov  = (const float*)d_in[7];
    const float* ua_Wp = (const float*)d_in[8];
    const float* ua_bp = (const float*)d_in[9];
    const float* ua_v  = (const float*)d_in[10];
    const float* ua_wc = (const float*)d_in[11];
    const float* ta_Wp = (const float*)d_in[12];
    const float* ta_bp = (const float*)d_in[13];
    const float* ta_v  = (const float*)d_in[14];
    const float* ta_wc = (const float*)d_in[15];
    const float* pgen_W= (const float*)d_in[16];
    const float* pgen_b= (const float*)d_in[17];
    const float* W1    = (const float*)d_in[18];
    const float* b1    = (const float*)d_in[19];
    const float* W2    = (const float*)d_in[20];
    const float* b2    = (const float*)d_in[21];
    const float* ln_g  = (const float*)d_in[22];
    const float* ln_b  = (const float*)d_in[23];

    float* out = (float*)d_out;
    float* o_vocab = out;
    float* o_tattn = o_vocab + (long)B*V;
    float* o_pgen  = o_tattn + B*TK;
    float* o_ucov  = o_pgen + B;
    float* o_ntc   = o_ucov + B*U;
    float* o_uidx  = o_ntc + (long)U*B*TK;

    cudaFuncSetAttribute(k_tatt, cudaFuncAttributeMaxDynamicSharedMemorySize, 49152);
    cudaFuncSetAttribute(k_vocab, cudaFuncAttributeMaxDynamicSharedMemorySize, 32*BSTRIDE*8);

    k_ln   <<<B, 256>>>(tf, ln_g, ln_b);
    k_proj <<<dim3(D/8, B/8, 2), 256>>>(ua_Wp, ua_bp, ta_Wp, ta_bp);
    k_uatt <<<B, 256>>>(enc, umask, cov, ua_wc, ua_v, pgen_W, pgen_b,
                        o_ucov, o_pgen, o_uidx);
    k_tatt <<<dim3(U, B), 256, 49152>>>(tok, tmask, tcov, ta_wc, ta_v, o_ntc, o_tattn);
    k_h    <<<dim3(D/8, B/8), 256>>>(W1, b1);
    k_vocab<<<(V+127)/128, 256, 32*BSTRIDE*8>>>(W2, b2);
    k_red  <<<B, 256>>>();
    k_soft <<<(int)(((long)B*V + 255)/256), 256>>>(o_vocab);
}

// round 8
// speedup vs baseline: 1.2722x; 1.2722x over previous
#include <cuda_runtime.h>
#include <cuda_bf16.h>

#define B   32
#define U   32
#define TK  64
#define TDEC 64
#define D   512
#define V   50257

// ---------------- scratch ----------------
__device__ float g_local_dec[B*D];
__device__ float g_dec_ua[B*D];
__device__ float g_dec_ta[B*D];
__device__ float g_target_out[B*D];
__device__ int   g_sel[B];
__device__ float g_logits[(long)B*V];
__device__ float g_m[B];
__device__ float g_inv_s[B];
__device__ unsigned g_hhi[B*256];   // [b][kpair] bf16x2 of h_hi
__device__ unsigned g_hlo[B*256];   // [b][kpair] bf16x2 of h_lo

// ---------------- helpers ----------------
__device__ __forceinline__ float ftanh(float x){
    float y; asm("tanh.approx.f32 %0, %1;" : "=f"(y) : "f"(x)); return y;
}
__device__ __forceinline__ float wsum(float v){
    #pragma unroll
    for (int o=16;o;o>>=1) v += __shfl_xor_sync(0xffffffffu, v, o);
    return v;
}
__device__ __forceinline__ float wmax(float v){
    #pragma unroll
    for (int o=16;o;o>>=1) v = fmaxf(v, __shfl_xor_sync(0xffffffffu, v, o));
    return v;
}
__device__ __forceinline__ unsigned smem_u32(const void* p){
    unsigned a;
    asm("{ .reg .u64 t; cvta.to.shared.u64 t, %1; cvt.u32.u64 %0, t; }" : "=r"(a) : "l"(p));
    return a;
}

// cp.async
#define CPA(dst, src) asm volatile("cp.async.cg.shared.global [%0], [%1], 16;" :: "r"(dst), "l"(src) : "memory")
#define CPC()  asm volatile("cp.async.commit_group;" ::: "memory")
#define CPW3() asm volatile("cp.async.wait_group 3;" ::: "memory")

// bf16 mma m16n8k16
__device__ __forceinline__ void mma16816(float* d, unsigned a0, unsigned a1,
                                         unsigned a2, unsigned a3,
                                         unsigned b0, unsigned b1){
    asm volatile("mma.sync.aligned.m16n8k16.row.col.f32.bf16.bf16.f32 "
        "{%0,%1,%2,%3}, {%4,%5,%6,%7}, {%8,%9}, {%0,%1,%2,%3};"
        : "+f"(d[0]), "+f"(d[1]), "+f"(d[2]), "+f"(d[3])
        : "r"(a0), "r"(a1), "r"(a2), "r"(a3), "r"(b0), "r"(b1));
}
__device__ __forceinline__ void cvt_hilo(float2 f, unsigned &hi, unsigned &lo){
    __nv_bfloat162 h = __float22bfloat162_rn(f);
    float2 fh = __bfloat1622float2(h);
    __nv_bfloat162 l = __float22bfloat162_rn(make_float2(f.x - fh.x, f.y - fh.y));
    hi = *(unsigned*)&h; lo = *(unsigned*)&l;
}

// ---------------- K1: layernorm ----------------
__global__ void k_ln(const float* __restrict__ tf, const float* __restrict__ g,
                     const float* __restrict__ bb){
    int b = blockIdx.x, tid = threadIdx.x;
    const float* row = tf + (b*TDEC + (TDEC-1))*D;
    float x0 = row[tid], x1 = row[tid+256];
    __shared__ float s1[256], s2[256];
    s1[tid] = x0+x1; s2[tid] = x0*x0 + x1*x1;
    __syncthreads();
    for (int o=128;o;o>>=1){
        if (tid<o){ s1[tid]+=s1[tid+o]; s2[tid]+=s2[tid+o]; }
        __syncthreads();
    }
    float mu = s1[0]*(1.0f/D);
    float var = s2[0]*(1.0f/D) - mu*mu;
    float r = rsqrtf(var + 1e-5f);
    g_local_dec[b*D+tid]     = (x0-mu)*r*g[tid]     + bb[tid];
    g_local_dec[b*D+tid+256] = (x1-mu)*r*g[tid+256] + bb[tid+256];
}

// ---------------- K2: dec projections (W rows in regs, 8 batches/block) ------
__global__ void k_proj(const float* __restrict__ ua_Wp, const float* __restrict__ ua_bp,
                       const float* __restrict__ ta_Wp, const float* __restrict__ ta_bp){
    int which = blockIdx.z;
    const float* W    = which ? ta_Wp : ua_Wp;
    const float* bias = which ? ta_bp : ua_bp;
    float* outp       = which ? g_dec_ta : g_dec_ua;
    int warp = threadIdx.x >> 5, lane = threadIdx.x & 31;
    int d = blockIdx.x*8 + warp;
    const float4* wrow = (const float4*)(W + (long)d*D);
    float4 w4[4];
    #pragma unroll
    for (int i=0;i<4;i++) w4[i] = wrow[i*32 + lane];
    float bval = bias[d];
    #pragma unroll
    for (int bi=0; bi<8; bi++){
        int b = blockIdx.y*8 + bi;
        const float4* t = (const float4*)(g_local_dec + b*D);
        float acc = 0.f;
        #pragma unroll
        for (int i=0;i<4;i++){
            float4 t4 = t[i*32 + lane];
            acc += w4[i].x*t4.x + w4[i].y*t4.y + w4[i].z*t4.z + w4[i].w*t4.w;
        }
        acc = wsum(acc);
        if (!lane) outp[b*D + d] = acc + bval;
    }
}

// ---------------- K3: utterance attention + argmax + p_gen ----------------
__global__ void k_uatt(const float* __restrict__ enc, const float* __restrict__ umask,
                       const float* __restrict__ cov, const float* __restrict__ ua_wc,
                       const float* __restrict__ ua_v, const float* __restrict__ pgen_W,
                       const float* __restrict__ pgen_b,
                       float* __restrict__ o_ucov, float* __restrict__ o_pgen,
                       float* __restrict__ o_uidx){
    int b = blockIdx.x, tid = threadIdx.x;
    int warp = tid>>5, lane = tid&31;
    __shared__ float s_scores[U], s_attn[U], s_red[256];
    float4 dec4[4], wc4[4], v4[4];
    #pragma unroll
    for (int i=0;i<4;i++){
        int d = i*128 + lane*4;
        dec4[i] = *(const float4*)(g_dec_ua + b*D + d);
        wc4[i]  = *(const float4*)(ua_wc + d);
        v4[i]   = *(const float4*)(ua_v + d);
    }
    #pragma unroll
    for (int uu=0; uu<4; uu++){
        int u = warp + uu*8;
        float c = cov[b*U + u];
        const float4* e = (const float4*)(enc + (long)(b*U + u)*D);
        float acc = 0.f;
        #pragma unroll
        for (int i=0;i<4;i++){
            float4 x = e[i*32 + lane];
            acc += ftanh(x.x + dec4[i].x + c*wc4[i].x) * v4[i].x;
            acc += ftanh(x.y + dec4[i].y + c*wc4[i].y) * v4[i].y;
            acc += ftanh(x.z + dec4[i].z + c*wc4[i].z) * v4[i].z;
            acc += ftanh(x.w + dec4[i].w + c*wc4[i].w) * v4[i].w;
        }
        acc = wsum(acc);
        if (!lane) s_scores[u] = acc;
    }
    __syncthreads();
    if (warp == 0){
        int u = lane;
        float s = s_scores[u];
        float m = wmax(s);
        float e = expf(s - m);
        float den = wsum(e);
        float a_ = (e/den) * umask[b*U+u];
        float nf = wsum(a_);
        float attn = a_ / (nf == 0.f ? 1.f : nf);
        s_attn[u] = attn;
        o_ucov[b*U+u] = cov[b*U+u] + attn;
        float bv = attn; int bi = u;
        #pragma unroll
        for (int o=16;o;o>>=1){
            float ov = __shfl_xor_sync(0xffffffffu, bv, o);
            int   oi = __shfl_xor_sync(0xffffffffu, bi, o);
            if (ov > bv || (ov == bv && oi < bi)){ bv = ov; bi = oi; }
        }
        if (!lane){ g_sel[b] = bi; o_uidx[b] = (float)bi; }
    }
    __syncthreads();
    float part = 0.f;
    #pragma unroll
    for (int j=0;j<2;j++){
        int d = tid + j*256;
        float acc = 0.f;
        #pragma unroll 8
        for (int u=0;u<U;u++) acc += s_attn[u] * enc[(long)(b*U+u)*D + d];
        part += pgen_W[d]*acc + pgen_W[D + d]*g_local_dec[b*D + d];
    }
    s_red[tid] = part;
    __syncthreads();
    for (int o=128;o;o>>=1){ if (tid<o) s_red[tid]+=s_red[tid+o]; __syncthreads(); }
    if (!tid) o_pgen[b] = 1.f/(1.f + expf(-(s_red[0] + pgen_b[0])));
}

// ---------------- K4: token attention (R5 exact: 4-stage ring, wait_group 3) --
__global__ void __launch_bounds__(256,3)
k_tatt(const float* __restrict__ tok, const float* __restrict__ tmask,
       const float* __restrict__ tcov, const float* __restrict__ ta_wc,
       const float* __restrict__ ta_v,
       float* __restrict__ o_ntc, float* __restrict__ o_tattn){
    extern __shared__ float ring[];   // 8 warps * 4 stages * 512 floats = 64KB
    __shared__ float s_scores[TK], s_attn[TK], s_cov[TK];
    int u = blockIdx.x, b = blockIdx.y;
    int tid = threadIdx.x, warp = tid>>5, lane = tid&31;
    int ub = u*B + b;
    float* wring = ring + warp*2048;
    unsigned rb = smem_u32(wring);
    const float* rowbase = tok + (long)ub*TK*D;
    if (tid < TK) s_cov[tid] = tcov[ub*TK + tid];

    float4 dec4[4], wc4[4], v4[4];
    #pragma unroll
    for (int i=0;i<4;i++){
        int d = i*128 + lane*4;
        dec4[i] = *(const float4*)(g_dec_ta + b*D + d);
        wc4[i]  = *(const float4*)(ta_wc + d);
        v4[i]   = *(const float4*)(ta_v + d);
    }
    #pragma unroll
    for (int s=0;s<3;s++){
        const float* src = rowbase + (warp*8+s)*D;
        #pragma unroll
        for (int i=0;i<4;i++)
            CPA(rb + (unsigned)(s*512 + (i*32+lane)*4)*4u, src + (i*32+lane)*4);
        CPC();
    }
    __syncthreads();   // s_cov ready
    #pragma unroll
    for (int tt=0; tt<8; tt++){
        if (tt < 5){
            const float* src = rowbase + (warp*8+tt+3)*D;
            int s = (tt+3)&3;
            #pragma unroll
            for (int i=0;i<4;i++)
                CPA(rb + (unsigned)(s*512 + (i*32+lane)*4)*4u, src + (i*32+lane)*4);
        }
        CPC();
        CPW3();
        float c = s_cov[warp*8+tt];
        const float4* xs = (const float4*)(wring + (tt&3)*512);
        float acc = 0.f;
        #pragma unroll
        for (int i=0;i<4;i++){
            float4 x = xs[i*32+lane];
            acc += ftanh(x.x + dec4[i].x + c*wc4[i].x)*v4[i].x;
            acc += ftanh(x.y + dec4[i].y + c*wc4[i].y)*v4[i].y;
            acc += ftanh(x.z + dec4[i].z + c*wc4[i].z)*v4[i].z;
            acc += ftanh(x.w + dec4[i].w + c*wc4[i].w)*v4[i].w;
        }
        acc = wsum(acc);
        if (!lane) s_scores[warp*8+tt] = acc;
    }
    __syncthreads();
    int sel = g_sel[b];
    if (warp == 0){
        float s0 = s_scores[lane], s1 = s_scores[lane+32];
        float m = wmax(fmaxf(s0,s1));
        float e0 = expf(s0-m), e1 = expf(s1-m);
        float den = wsum(e0+e1);
        float a0 = (e0/den)*tmask[ub*TK+lane];
        float a1 = (e1/den)*tmask[ub*TK+lane+32];
        float nf = wsum(a0+a1);
        float inv = 1.f/((nf==0.f)?1.f:nf);
        a0 *= inv; a1 *= inv;
        s_attn[lane] = a0; s_attn[lane+32] = a1;
        o_ntc[ub*TK+lane]    = s_cov[lane]    + a0;
        o_ntc[ub*TK+lane+32] = s_cov[lane+32] + a1;
        if (u == sel){ o_tattn[b*TK+lane] = a0; o_tattn[b*TK+lane+32] = a1; }
    }
    __syncthreads();
    if (u == sel){
        #pragma unroll
        for (int j=0;j<2;j++){
            int d = tid + j*256;
            float acc = 0.f;
            #pragma unroll 8
            for (int t=0;t<TK;t++) acc += s_attn[t]*tok[(long)ub*TK*D + t*D + d];
            g_target_out[b*D + d] = acc;
        }
    }
}

// ---------------- K5: h -> bf16 hi/lo (W1 rows in regs, 8 batches/block) -----
__global__ void k_h(const float* __restrict__ W1, const float* __restrict__ b1){
    int warp = threadIdx.x>>5, lane = threadIdx.x&31;
    int d = blockIdx.x*8 + warp;
    const float4* w = (const float4*)(W1 + (long)d*2*D);
    float4 w4[8];
    #pragma unroll
    for (int i=0;i<8;i++) w4[i] = w[i*32+lane];
    float bval = b1[d];
    #pragma unroll
    for (int bi=0; bi<8; bi++){
        int b = blockIdx.y*8 + bi;
        const float4* t0 = (const float4*)(g_target_out + b*D);
        const float4* t1 = (const float4*)(g_local_dec + b*D);
        float acc=0.f;
        #pragma unroll
        for (int i=0;i<4;i++){
            float4 x = t0[i*32+lane];
            acc += w4[i].x*x.x + w4[i].y*x.y + w4[i].z*x.z + w4[i].w*x.w;
        }
        #pragma unroll
        for (int i=0;i<4;i++){
            float4 x = t1[i*32+lane];
            acc += w4[i+4].x*x.x + w4[i+4].y*x.y + w4[i+4].z*x.z + w4[i+4].w*x.w;
        }
        acc = wsum(acc);
        if (!lane){
            float h = acc + bval;
            __nv_bfloat16 hi = __float2bfloat16(h);
            __nv_bfloat16 lo = __float2bfloat16(h - __bfloat162float(hi));
            ((__nv_bfloat16*)g_hhi)[b*512 + d] = hi;
            ((__nv_bfloat16*)g_hlo)[b*512 + d] = lo;
        }
    }
}

// ---------------- K6: vocab GEMM via mma.sync (R5 exact: depth-1 prefetch) ---
#define BSTRIDE 260
__global__ void __launch_bounds__(256)
k_vocab(const float* __restrict__ W2, const float* __restrict__ b2){
    extern __shared__ uint2 sB[];   // 32 * 260 * 8B = 66560 B
    int tid = threadIdx.x, wm = tid>>5, lane = tid&31;
    int g = lane>>2, tg = lane&3;
    int v0 = blockIdx.x * 128;

    for (int i = tid; i < 32*256; i += 256){
        int n = i >> 8, kp = i & 255;
        sB[n*BSTRIDE + kp] = make_uint2(g_hhi[i], g_hlo[i]);
    }
    __syncthreads();

    int r0 = v0 + wm*16 + g;
    int r1 = r0 + 8;
    const float* w0 = W2 + (long)(r0 < V ? r0 : V-1)*D;
    const float* w1 = W2 + (long)(r1 < V ? r1 : V-1)*D;

    float dd[4][4];
    #pragma unroll
    for (int nt=0;nt<4;nt++){ dd[nt][0]=dd[nt][1]=dd[nt][2]=dd[nt][3]=0.f; }

    int c0 = tg*2;
    float2 pa0 = *(const float2*)(w0 + c0);
    float2 pa1 = *(const float2*)(w1 + c0);
    float2 pa2 = *(const float2*)(w0 + c0 + 8);
    float2 pa3 = *(const float2*)(w1 + c0 + 8);

    #pragma unroll 4
    for (int ks=0; ks<32; ks++){
        float2 ca0=pa0, ca1=pa1, ca2=pa2, ca3=pa3;
        int kn = ((ks+1)&31)*16 + c0;
        pa0 = *(const float2*)(w0 + kn);
        pa1 = *(const float2*)(w1 + kn);
        pa2 = *(const float2*)(w0 + kn + 8);
        pa3 = *(const float2*)(w1 + kn + 8);

        unsigned ah0,al0,ah1,al1,ah2,al2,ah3,al3;
        cvt_hilo(ca0, ah0, al0);
        cvt_hilo(ca1, ah1, al1);
        cvt_hilo(ca2, ah2, al2);
        cvt_hilo(ca3, ah3, al3);

        int kp = ks*8 + tg;
        #pragma unroll
        for (int nt=0; nt<4; nt++){
            int nrow = (nt*8 + g)*BSTRIDE;
            uint2 b0 = sB[nrow + kp];
            uint2 b1 = sB[nrow + kp + 4];
            mma16816(dd[nt], ah0, ah1, ah2, ah3, b0.x, b1.x);  // hi*hi
            mma16816(dd[nt], al0, al1, al2, al3, b0.x, b1.x);  // lo*hi
            mma16816(dd[nt], ah0, ah1, ah2, ah3, b0.y, b1.y);  // hi*lo
        }
    }

    float bias0 = (r0 < V) ? b2[r0] : 0.f;
    float bias1 = (r1 < V) ? b2[r1] : 0.f;
    #pragma unroll
    for (int nt=0; nt<4; nt++){
        int n = nt*8 + tg*2;
        if (r0 < V){
            g_logits[(long)n*V + r0]     = dd[nt][0] + bias0;
            g_logits[(long)(n+1)*V + r0] = dd[nt][1] + bias0;
        }
        if (r1 < V){
            g_logits[(long)n*V + r1]     = dd[nt][2] + bias1;
            g_logits[(long)(n+1)*V + r1] = dd[nt][3] + bias1;
        }
    }
}

// ---------------- K7: softmax stats ----------------
__global__ void k_red(){
    int b = blockIdx.x, tid = threadIdx.x;
    __shared__ float sm[256];
    const float* L = g_logits + (long)b*V;
    float m = -1e30f;
    for (int v=tid; v<V; v+=256) m = fmaxf(m, L[v]);
    sm[tid]=m; __syncthreads();
    for (int o=128;o;o>>=1){ if (tid<o) sm[tid]=fmaxf(sm[tid],sm[tid+o]); __syncthreads(); }
    m = sm[0]; __syncthreads();
    float s=0.f;
    for (int v=tid; v<V; v+=256) s += expf(L[v]-m);
    sm[tid]=s; __syncthreads();
    for (int o=128;o;o>>=1){ if (tid<o) sm[tid]+=sm[tid+o]; __syncthreads(); }
    if (!tid){ g_m[b]=m; g_inv_s[b] = 1.f/sm[0]; }
}

// ---------------- K8: vocab_dist ----------------
__global__ void k_soft(float* __restrict__ o_vocab){
    long i = (long)blockIdx.x*256 + threadIdx.x;
    if (i >= (long)B*V) return;
    int b = (int)(i / V);
    o_vocab[i] = expf(g_logits[i] - g_m[b]) * g_inv_s[b];
}

// ---------------- launch ----------------
extern "C" void kernel_launch(void* const* d_in, const int* in_sizes, int n_in,
                              void* d_out, int out_size){
    const float* tf    = (const float*)d_in[0];
    const float* enc   = (const float*)d_in[2];
    const float* umask = (const float*)d_in[3];
    const float* tok   = (const float*)d_in[4];
    const float* tmask = (const float*)d_in[5];
    const float* cov   = (const float*)d_in[6];
    const float* tcov  = (const float*)d_in[7];
    const float* ua_Wp = (const float*)d_in[8];
    const float* ua_bp = (const float*)d_in[9];
    const float* ua_v  = (const float*)d_in[10];
    const float* ua_wc = (const float*)d_in[11];
    const float* ta_Wp = (const float*)d_in[12];
    const float* ta_bp = (const float*)d_in[13];
    const float* ta_v  = (const float*)d_in[14];
    const float* ta_wc = (const float*)d_in[15];
    const float* pgen_W= (const float*)d_in[16];
    const float* pgen_b= (const float*)d_in[17];
    const float* W1    = (const float*)d_in[18];
    const float* b1    = (const float*)d_in[19];
    const float* W2    = (const float*)d_in[20];
    const float* b2    = (const float*)d_in[21];
    const float* ln_g  = (const float*)d_in[22];
    const float* ln_b  = (const float*)d_in[23];

    float* out = (float*)d_out;
    float* o_vocab = out;
    float* o_tattn = o_vocab + (long)B*V;
    float* o_pgen  = o_tattn + B*TK;
    float* o_ucov  = o_pgen + B;
    float* o_ntc   = o_ucov + B*U;
    float* o_uidx  = o_ntc + (long)U*B*TK;

    cudaFuncSetAttribute(k_tatt, cudaFuncAttributeMaxDynamicSharedMemorySize, 65536);
    cudaFuncSetAttribute(k_vocab, cudaFuncAttributeMaxDynamicSharedMemorySize, 32*BSTRIDE*8);

    k_ln   <<<B, 256>>>(tf, ln_g, ln_b);
    k_proj <<<dim3(D/8, B/8, 2), 256>>>(ua_Wp, ua_bp, ta_Wp, ta_bp);
    k_uatt <<<B, 256>>>(enc, umask, cov, ua_wc, ua_v, pgen_W, pgen_b,
                        o_ucov, o_pgen, o_uidx);
    k_tatt <<<dim3(U, B), 256, 65536>>>(tok, tmask, tcov, ta_wc, ta_v, o_ntc, o_tattn);
    k_h    <<<dim3(D/8, B/8), 256>>>(W1, b1);
    k_vocab<<<(V+127)/128, 256, 32*BSTRIDE*8>>>(W2, b2);
    k_red  <<<B, 256>>>();
    k_soft <<<(int)(((long)B*V + 255)/256), 256>>>(o_vocab);
}